// round 12
// baseline (speedup 1.0000x reference)
#include <cuda_runtime.h>
#include <cstdint>
#include <math.h>

// ---------------- problem constants ----------------
#define BATCH 2
#define SEQ   2048
#define DM    1024
#define NH    16
#define DH    64
#define MROWS (BATCH*SEQ)   // 4096

// ---------------- scratch ----------------
__device__ float g_Q[(size_t)BATCH*NH*SEQ*DH];
__device__ float g_K[(size_t)BATCH*NH*SEQ*DH];
__device__ float g_V[(size_t)BATCH*NH*SEQ*DH];
__device__ float g_A[(size_t)BATCH*SEQ*DM];
// pre-rounded (tf32) copies of inputs
__device__ float g_X [(size_t)MROWS*DM];
__device__ float g_Wq[(size_t)DM*DM];
__device__ float g_Wk[(size_t)DM*DM];
__device__ float g_Wv[(size_t)DM*DM];
__device__ float g_Wo[(size_t)DM*DM];

// round-to-nearest fp32 -> tf32
__device__ __forceinline__ float tf32r(float x) {
    uint32_t u = __float_as_uint(x);
    uint32_t r = (u + 0xFFFu + ((u >> 13) & 1u)) & 0xFFFFE000u;
    return __uint_as_float(r);
}
__device__ __forceinline__ uint32_t cvt_tf32(float x) {
    uint32_t r;
    asm("cvt.rna.tf32.f32 %0, %1;" : "=r"(r) : "f"(x));
    return r;
}

__device__ __forceinline__ void mma_tf32(float* d, const uint32_t* a, uint32_t b0, uint32_t b1) {
    asm volatile(
        "mma.sync.aligned.m16n8k8.row.col.f32.tf32.tf32.f32 "
        "{%0,%1,%2,%3}, {%4,%5,%6,%7}, {%8,%9}, {%0,%1,%2,%3};"
        : "+f"(d[0]), "+f"(d[1]), "+f"(d[2]), "+f"(d[3])
        : "r"(a[0]), "r"(a[1]), "r"(a[2]), "r"(a[3]), "r"(b0), "r"(b1));
}

// ---------------- prepass: tf32-round x and weights once ----------------
#define NX ((size_t)MROWS*DM)        // 4194304
#define NW ((size_t)DM*DM)           // 1048576
#define NTOT (NX + 4*NW)             // 8388608 floats

__global__ __launch_bounds__(256)
void prep_kernel(const float* __restrict__ x,
                 const float* __restrict__ Wq, const float* __restrict__ Wk,
                 const float* __restrict__ Wv, const float* __restrict__ Wo,
                 float* __restrict__ gx,
                 float* __restrict__ gwq, float* __restrict__ gwk,
                 float* __restrict__ gwv, float* __restrict__ gwo)
{
    size_t v = (size_t)blockIdx.x * blockDim.x + threadIdx.x;   // float4 index
    const size_t nx4 = NX / 4, nw4 = NW / 4;
    if (v >= NTOT / 4) return;
    const float4* src; float4* dst; size_t off;
    if (v < nx4)                { src = (const float4*)x;  dst = (float4*)gx;  off = v; }
    else if (v < nx4 + nw4)     { src = (const float4*)Wq; dst = (float4*)gwq; off = v - nx4; }
    else if (v < nx4 + 2*nw4)   { src = (const float4*)Wk; dst = (float4*)gwk; off = v - nx4 - nw4; }
    else if (v < nx4 + 3*nw4)   { src = (const float4*)Wv; dst = (float4*)gwv; off = v - nx4 - 2*nw4; }
    else                        { src = (const float4*)Wo; dst = (float4*)gwo; off = v - nx4 - 3*nw4; }
    float4 a = src[off];
    a.x = tf32r(a.x); a.y = tf32r(a.y); a.z = tf32r(a.z); a.w = tf32r(a.w);
    dst[off] = a;
}

// ---------------- HMMA tf32 GEMM body (inputs pre-rounded) ----------------
#define GM 128
#define GN 128
#define GKC 32
#define NCHUNK (DM/GKC)

#define SM_BIAS 0
#define SM_A0   128
#define SM_B0   (SM_A0 + 4096)
#define SM_A1   (SM_B0 + 4096)
#define SM_B1   (SM_A1 + 4096)
#define GSMEM_FLOATS (SM_B1 + 4096)
#define GSMEM_BYTES  (GSMEM_FLOATS * 4)

// modes: 0 = row-major (final O-proj); 1 = rotate+round (K); 2 = round (V); 3 = rotate+scale+round (Q)
__device__ __forceinline__
void gemm_body(float* sm, const float* __restrict__ A, const float* __restrict__ W,
               const float* __restrict__ bias, float* __restrict__ C, int mode)
{
    const int tid  = threadIdx.x;
    const int lane = tid & 31;
    const int wid  = tid >> 5;
    const int wm   = wid & 3;
    const int wn   = wid >> 2;
    const int m0   = blockIdx.y * GM;
    const int n0   = blockIdx.x * GN;

    if (tid < 128) sm[SM_BIAS + tid] = bias[n0 + tid];

    int l_row[4], l_q[4];
    #pragma unroll
    for (int i = 0; i < 4; i++) { int idx = i * 256 + tid; l_row[i] = idx >> 3; l_q[i] = idx & 7; }

    float4 ra[4], rw[4];
    {
        const float* Ac = A + (size_t)m0 * DM;
        const float* Wc = W + (size_t)n0 * DM;
        #pragma unroll
        for (int i = 0; i < 4; i++) {
            ra[i] = *(const float4*)(Ac + (size_t)l_row[i] * DM + l_q[i] * 4);
            rw[i] = *(const float4*)(Wc + (size_t)l_row[i] * DM + l_q[i] * 4);
        }
    }
    #pragma unroll
    for (int i = 0; i < 4; i++) {
        const int row = l_row[i], q = l_q[i];
        const int ks = q >> 1, rh = q & 1;
        {
            const int mt = row >> 4, r = row & 15;
            float* ab = sm + SM_A0 + (mt * 4 + ks) * 128 + ((r >> 3) & 1) + (rh << 1);
            const float v[4] = {ra[i].x, ra[i].y, ra[i].z, ra[i].w};
            #pragma unroll
            for (int j = 0; j < 4; j++) ab[(((r & 7) << 2) | j) * 4] = v[j];
        }
        {
            const int nt = row >> 3, g = row & 7;
            float* bb = sm + SM_B0 + (nt * 4 + ks) * 64 + rh;
            const float v[4] = {rw[i].x, rw[i].y, rw[i].z, rw[i].w};
            #pragma unroll
            for (int j = 0; j < 4; j++) bb[(((g) << 2) | j) * 2] = v[j];
        }
    }
    __syncthreads();

    float acc[2][8][4];
    #pragma unroll
    for (int mt = 0; mt < 2; mt++)
        #pragma unroll
        for (int nt = 0; nt < 8; nt++)
            #pragma unroll
            for (int e = 0; e < 4; e++) acc[mt][nt][e] = 0.f;

    for (int c = 0; c < NCHUNK; c++) {
        const int p = c & 1;
        const float* Ab = sm + (p ? SM_A1 : SM_A0);
        const float* Bb = sm + (p ? SM_B1 : SM_B0);

        if (c + 1 < NCHUNK) {
            const float* Ac = A + (size_t)m0 * DM + (c + 1) * GKC;
            const float* Wc = W + (size_t)n0 * DM + (c + 1) * GKC;
            #pragma unroll
            for (int i = 0; i < 4; i++) {
                ra[i] = *(const float4*)(Ac + (size_t)l_row[i] * DM + l_q[i] * 4);
                rw[i] = *(const float4*)(Wc + (size_t)l_row[i] * DM + l_q[i] * 4);
            }
        }

        #pragma unroll
        for (int ks = 0; ks < 4; ks++) {
            uint32_t afr[2][4];
            #pragma unroll
            for (int mt = 0; mt < 2; mt++) {
                const int mtg = wm * 2 + mt;
                float4 av = *(const float4*)(Ab + (mtg * 4 + ks) * 128 + lane * 4);
                afr[mt][0] = __float_as_uint(av.x); afr[mt][1] = __float_as_uint(av.y);
                afr[mt][2] = __float_as_uint(av.z); afr[mt][3] = __float_as_uint(av.w);
            }
            uint32_t bfr[8][2];
            #pragma unroll
            for (int nt = 0; nt < 8; nt++) {
                const int ntg = wn * 8 + nt;
                float2 bv = *(const float2*)(Bb + (ntg * 4 + ks) * 64 + lane * 2);
                bfr[nt][0] = __float_as_uint(bv.x); bfr[nt][1] = __float_as_uint(bv.y);
            }
            #pragma unroll
            for (int mt = 0; mt < 2; mt++)
                #pragma unroll
                for (int nt = 0; nt < 8; nt++)
                    mma_tf32(acc[mt][nt], afr[mt], bfr[nt][0], bfr[nt][1]);
        }

        if (c + 1 < NCHUNK) {
            float* An = sm + (p ? SM_A0 : SM_A1);
            float* Bn = sm + (p ? SM_B0 : SM_B1);
            #pragma unroll
            for (int i = 0; i < 4; i++) {
                const int row = l_row[i], q = l_q[i];
                const int ks = q >> 1, rh = q & 1;
                {
                    const int mt = row >> 4, r = row & 15;
                    float* ab = An + (mt * 4 + ks) * 128 + ((r >> 3) & 1) + (rh << 1);
                    const float v[4] = {ra[i].x, ra[i].y, ra[i].z, ra[i].w};
                    #pragma unroll
                    for (int j = 0; j < 4; j++) ab[(((r & 7) << 2) | j) * 4] = v[j];
                }
                {
                    const int nt = row >> 3, g = row & 7;
                    float* bb = Bn + (nt * 4 + ks) * 64 + rh;
                    const float v[4] = {rw[i].x, rw[i].y, rw[i].z, rw[i].w};
                    #pragma unroll
                    for (int j = 0; j < 4; j++) bb[(((g) << 2) | j) * 2] = v[j];
                }
            }
        }
        __syncthreads();
    }

    const int g = lane >> 2, t = lane & 3;
    const float* bs = sm + SM_BIAS;

    #pragma unroll
    for (int mt = 0; mt < 2; mt++) {
        #pragma unroll
        for (int nt = 0; nt < 8; nt++) {
            const int colL = wn * 64 + nt * 8 + t * 2;
            const int col  = n0 + colL;
            #pragma unroll
            for (int half = 0; half < 2; half++) {
                const int m = m0 + wm * 32 + mt * 16 + g + half * 8;
                float y0 = acc[mt][nt][half * 2 + 0] + bs[colL];
                float y1 = acc[mt][nt][half * 2 + 1] + bs[colL + 1];
                if (mode == 0) {
                    *(float2*)(C + (size_t)m * DM + col) = make_float2(y0, y1);
                } else {
                    const int b  = m >> 11;
                    const int ts = m & 2047;
                    const int h  = col >> 6;
                    const int dh = col & 63;
                    float2 o;
                    if (mode == 3)      o = make_float2(tf32r(-y1 * 0.125f), tf32r(y0 * 0.125f));
                    else if (mode == 1) o = make_float2(tf32r(-y1), tf32r(y0));
                    else                o = make_float2(tf32r(y0),  tf32r(y1));
                    *(float2*)(C + (((size_t)(b * NH + h) * SEQ) + ts) * DH + dh) = o;
                }
            }
        }
    }
}

// fused QKV: grid.z selects projection
__global__ __launch_bounds__(256)
void gemm_qkv_kernel(const float* __restrict__ x,
                     const float* __restrict__ Wq, const float* __restrict__ bq,
                     const float* __restrict__ Wk, const float* __restrict__ bk,
                     const float* __restrict__ Wv, const float* __restrict__ bv,
                     float* __restrict__ Qo, float* __restrict__ Ko, float* __restrict__ Vo)
{
    extern __shared__ float sm[];
    const int z = blockIdx.z;
    const float* W    = (z == 0) ? Wq : (z == 1) ? Wk : Wv;
    const float* bias = (z == 0) ? bq : (z == 1) ? bk : bv;
    float* C          = (z == 0) ? Qo : (z == 1) ? Ko : Vo;
    gemm_body(sm, x, W, bias, C, (z == 0) ? 3 : (z == 1) ? 1 : 2);
}

__global__ __launch_bounds__(256)
void gemm_o_kernel(const float* __restrict__ A, const float* __restrict__ W,
                   const float* __restrict__ bias, float* __restrict__ C)
{
    extern __shared__ float sm[];
    gemm_body(sm, A, W, bias, C, 0);
}

// ---------------- HMMA tf32 flash attention (inputs pre-rounded & pre-scaled) ----------------
#define AQ_LD 68
#define AK_LD 68
#define AV_LD 72
#define A_OFF_Q 0
#define A_OFF_K (128*AQ_LD)
#define A_OFF_V (A_OFF_K + 64*AK_LD)
#define A_SMEM_FLOATS (A_OFF_V + 64*AV_LD)
#define A_SMEM_BYTES (A_SMEM_FLOATS*4)      // 70656

__global__ __launch_bounds__(128, 3)
void attn_mma_kernel(const float* __restrict__ Q, const float* __restrict__ K,
                     const float* __restrict__ V, float* __restrict__ O)
{
    extern __shared__ float sm[];
    float* Qs = sm + A_OFF_Q;
    float* Ks = sm + A_OFF_K;
    float* Vs = sm + A_OFF_V;

    const int tid  = threadIdx.x;
    const int lane = tid & 31;
    const int w    = tid >> 5;
    const int g    = lane >> 2;
    const int t    = lane & 3;
    const int bh   = blockIdx.y;
    const int qb   = (gridDim.x - 1) - blockIdx.x;   // heavy blocks first
    const int qblk = qb * 128;

    const float* Qg = Q + (size_t)bh * SEQ * DH;
    const float* Kg = K + (size_t)bh * SEQ * DH;
    const float* Vg = V + (size_t)bh * SEQ * DH;

    // ---- stage Q: pure copy (pre-scaled, pre-rounded), coalesced float4 ----
    {
        const float* src = Qg + (size_t)qblk * DH;
        #pragma unroll
        for (int j = 0; j < 16; j++) {
            const int f = (tid + j * 128) * 4;
            const int row = f >> 6, d = f & 63;
            *(float4*)(Qs + row * AQ_LD + d) = *(const float4*)(src + f);
        }
    }

    float o[2][8][4];
    #pragma unroll
    for (int mt = 0; mt < 2; mt++)
        #pragma unroll
        for (int nt = 0; nt < 8; nt++)
            #pragma unroll
            for (int e = 0; e < 4; e++) o[mt][nt][e] = 0.f;
    float mrow[2][2] = {{-1e30f, -1e30f}, {-1e30f, -1e30f}};
    float lrow[2][2] = {{0.f, 0.f}, {0.f, 0.f}};

    const int ntiles = 2 * qb + 2;
    const int wrow   = qblk + w * 32;
    const int wmax   = wrow + 31;

    for (int kt = 0; kt < ntiles; kt++) {
        const int kbase = kt * 64;
        __syncthreads();
        // ---- stage K/V tiles: pure copies, float4 in/out ----
        {
            const float* ksrc = Kg + (size_t)kbase * DH;
            const float* vsrc = Vg + (size_t)kbase * DH;
            #pragma unroll
            for (int j = 0; j < 8; j++) {
                const int f = (tid + j * 128) * 4;
                const int key = f >> 6, d = f & 63;
                *(float4*)(Ks + key * AK_LD + d) = *(const float4*)(ksrc + f);
                *(float4*)(Vs + key * AV_LD + d) = *(const float4*)(vsrc + f);
            }
        }
        __syncthreads();
        if (kbase > wmax) continue;

        // ---- S = Q K^T ----
        float s[2][8][4];
        #pragma unroll
        for (int mt = 0; mt < 2; mt++)
            #pragma unroll
            for (int nt = 0; nt < 8; nt++)
                #pragma unroll
                for (int e = 0; e < 4; e++) s[mt][nt][e] = 0.f;

        #pragma unroll
        for (int ks = 0; ks < 8; ks++) {
            uint32_t af[2][4];
            #pragma unroll
            for (int mt = 0; mt < 2; mt++) {
                const int r0 = w * 32 + mt * 16 + g;
                af[mt][0] = __float_as_uint(Qs[(r0    ) * AQ_LD + ks*8 + t    ]);
                af[mt][1] = __float_as_uint(Qs[(r0 + 8) * AQ_LD + ks*8 + t    ]);
                af[mt][2] = __float_as_uint(Qs[(r0    ) * AQ_LD + ks*8 + t + 4]);
                af[mt][3] = __float_as_uint(Qs[(r0 + 8) * AQ_LD + ks*8 + t + 4]);
            }
            #pragma unroll
            for (int nt = 0; nt < 8; nt++) {
                uint32_t b0 = __float_as_uint(Ks[(nt*8 + g) * AK_LD + ks*8 + t    ]);
                uint32_t b1 = __float_as_uint(Ks[(nt*8 + g) * AK_LD + ks*8 + t + 4]);
                mma_tf32(s[0][nt], af[0], b0, b1);
                mma_tf32(s[1][nt], af[1], b0, b1);
            }
        }

        // ---- causal mask ----
        if (kbase + 63 > wrow) {
            #pragma unroll
            for (int mt = 0; mt < 2; mt++) {
                const int r0 = wrow + mt * 16 + g;
                const int r1 = r0 + 8;
                #pragma unroll
                for (int nt = 0; nt < 8; nt++) {
                    const int key = kbase + nt * 8 + 2 * t;
                    if (key     > r0) s[mt][nt][0] = -1e30f;
                    if (key + 1 > r0) s[mt][nt][1] = -1e30f;
                    if (key     > r1) s[mt][nt][2] = -1e30f;
                    if (key + 1 > r1) s[mt][nt][3] = -1e30f;
                }
            }
        }

        // ---- online softmax ----
        #pragma unroll
        for (int mt = 0; mt < 2; mt++) {
            float mx0 = -1e30f, mx1 = -1e30f;
            #pragma unroll
            for (int nt = 0; nt < 8; nt++) {
                mx0 = fmaxf(mx0, fmaxf(s[mt][nt][0], s[mt][nt][1]));
                mx1 = fmaxf(mx1, fmaxf(s[mt][nt][2], s[mt][nt][3]));
            }
            mx0 = fmaxf(mx0, __shfl_xor_sync(0xFFFFFFFFu, mx0, 1));
            mx0 = fmaxf(mx0, __shfl_xor_sync(0xFFFFFFFFu, mx0, 2));
            mx1 = fmaxf(mx1, __shfl_xor_sync(0xFFFFFFFFu, mx1, 1));
            mx1 = fmaxf(mx1, __shfl_xor_sync(0xFFFFFFFFu, mx1, 2));
            const float mn0 = fmaxf(mrow[mt][0], mx0);
            const float mn1 = fmaxf(mrow[mt][1], mx1);
            const float c0 = __expf(mrow[mt][0] - mn0);
            const float c1 = __expf(mrow[mt][1] - mn1);
            lrow[mt][0] *= c0; lrow[mt][1] *= c1;
            #pragma unroll
            for (int nt = 0; nt < 8; nt++) {
                o[mt][nt][0] *= c0; o[mt][nt][1] *= c0;
                o[mt][nt][2] *= c1; o[mt][nt][3] *= c1;
            }
            mrow[mt][0] = mn0; mrow[mt][1] = mn1;
            float rs0 = 0.f, rs1 = 0.f;
            #pragma unroll
            for (int nt = 0; nt < 8; nt++) {
                s[mt][nt][0] = __expf(s[mt][nt][0] - mn0);
                s[mt][nt][1] = __expf(s[mt][nt][1] - mn0);
                s[mt][nt][2] = __expf(s[mt][nt][2] - mn1);
                s[mt][nt][3] = __expf(s[mt][nt][3] - mn1);
                rs0 += s[mt][nt][0] + s[mt][nt][1];
                rs1 += s[mt][nt][2] + s[mt][nt][3];
            }
            rs0 += __shfl_xor_sync(0xFFFFFFFFu, rs0, 1);
            rs0 += __shfl_xor_sync(0xFFFFFFFFu, rs0, 2);
            rs1 += __shfl_xor_sync(0xFFFFFFFFu, rs1, 1);
            rs1 += __shfl_xor_sync(0xFFFFFFFFu, rs1, 2);
            lrow[mt][0] += rs0; lrow[mt][1] += rs1;
        }

        // ---- O += P V : transpose P frags via shfl, mma against V (row-major) ----
        const int src1 = (g << 2) | (t >> 1);
        const int src2 = src1 + 2;
        const bool odd = (t & 1) != 0;
        #pragma unroll
        for (int ks = 0; ks < 8; ks++) {
            uint32_t af[2][4];
            #pragma unroll
            for (int mt = 0; mt < 2; mt++) {
                float e0 = __shfl_sync(0xFFFFFFFFu, s[mt][ks][0], src1);
                float e1 = __shfl_sync(0xFFFFFFFFu, s[mt][ks][1], src1);
                float e2 = __shfl_sync(0xFFFFFFFFu, s[mt][ks][2], src1);
                float e3 = __shfl_sync(0xFFFFFFFFu, s[mt][ks][3], src1);
                float f0 = __shfl_sync(0xFFFFFFFFu, s[mt][ks][0], src2);
                float f1 = __shfl_sync(0xFFFFFFFFu, s[mt][ks][1], src2);
                float f2 = __shfl_sync(0xFFFFFFFFu, s[mt][ks][2], src2);
                float f3 = __shfl_sync(0xFFFFFFFFu, s[mt][ks][3], src2);
                af[mt][0] = cvt_tf32(odd ? e1 : e0);
                af[mt][1] = cvt_tf32(odd ? e3 : e2);
                af[mt][2] = cvt_tf32(odd ? f1 : f0);
                af[mt][3] = cvt_tf32(odd ? f3 : f2);
            }
            #pragma unroll
            for (int dnt = 0; dnt < 8; dnt++) {
                uint32_t b0 = __float_as_uint(Vs[(ks*8 + t    ) * AV_LD + dnt*8 + g]);
                uint32_t b1 = __float_as_uint(Vs[(ks*8 + t + 4) * AV_LD + dnt*8 + g]);
                mma_tf32(o[0][dnt], af[0], b0, b1);
                mma_tf32(o[1][dnt], af[1], b0, b1);
            }
        }
    }

    // ---- normalize + tf32-round + write [b][t][h*64+dh] (feeds gemm_o directly) ----
    const int b = bh >> 4, h = bh & 15;
    #pragma unroll
    for (int mt = 0; mt < 2; mt++) {
        const float i0 = 1.f / lrow[mt][0];
        const float i1 = 1.f / lrow[mt][1];
        const int r0 = wrow + mt * 16 + g;
        const int r1 = r0 + 8;
        #pragma unroll
        for (int dnt = 0; dnt < 8; dnt++) {
            const int col = h * 64 + dnt * 8 + 2 * t;
            *(float2*)(O + ((size_t)(b * SEQ + r0)) * DM + col) =
                make_float2(tf32r(o[mt][dnt][0] * i0), tf32r(o[mt][dnt][1] * i0));
            *(float2*)(O + ((size_t)(b * SEQ + r1)) * DM + col) =
                make_float2(tf32r(o[mt][dnt][2] * i1), tf32r(o[mt][dnt][3] * i1));
        }
    }
}

// ---------------- launcher ----------------
extern "C" void kernel_launch(void* const* d_in, const int* in_sizes, int n_in,
                              void* d_out, int out_size)
{
    const float* x  = (const float*)d_in[0];
    const float* Wq = (const float*)d_in[1];
    const float* bq = (const float*)d_in[2];
    const float* Wk = (const float*)d_in[3];
    const float* bk = (const float*)d_in[4];
    const float* Wv = (const float*)d_in[5];
    const float* bv = (const float*)d_in[6];
    const float* Wo = (const float*)d_in[7];
    const float* bo = (const float*)d_in[8];
    float* out = (float*)d_out;

    float *qp, *kp, *vp, *ap, *xp, *wqp, *wkp, *wvp, *wop;
    cudaGetSymbolAddress((void**)&qp,  g_Q);
    cudaGetSymbolAddress((void**)&kp,  g_K);
    cudaGetSymbolAddress((void**)&vp,  g_V);
    cudaGetSymbolAddress((void**)&ap,  g_A);
    cudaGetSymbolAddress((void**)&xp,  g_X);
    cudaGetSymbolAddress((void**)&wqp, g_Wq);
    cudaGetSymbolAddress((void**)&wkp, g_Wk);
    cudaGetSymbolAddress((void**)&wvp, g_Wv);
    cudaGetSymbolAddress((void**)&wop, g_Wo);

    cudaFuncSetAttribute(gemm_qkv_kernel, cudaFuncAttributeMaxDynamicSharedMemorySize, GSMEM_BYTES);
    cudaFuncSetAttribute(gemm_o_kernel,  cudaFuncAttributeMaxDynamicSharedMemorySize, GSMEM_BYTES);
    cudaFuncSetAttribute(attn_mma_kernel, cudaFuncAttributeMaxDynamicSharedMemorySize, A_SMEM_BYTES);

    // prepass: round x + weights to tf32 once
    {
        const int nthreads = 256;
        const int nblocks = (int)((NTOT / 4 + nthreads - 1) / nthreads);
        prep_kernel<<<nblocks, nthreads>>>(x, Wq, Wk, Wv, Wo, xp, wqp, wkp, wvp, wop);
    }

    dim3 gq(DM / GN, MROWS / GM, 3);   // (8, 32, 3) -> 768 CTAs
    gemm_qkv_kernel<<<gq, 256, GSMEM_BYTES>>>(xp, wqp, bq, wkp, bk, wvp, bv, qp, kp, vp);

    attn_mma_kernel<<<dim3(SEQ / 128, BATCH * NH), 128, A_SMEM_BYTES>>>(qp, kp, vp, ap);

    dim3 gg(DM / GN, MROWS / GM);      // (8, 32)
    gemm_o_kernel<<<gg, 256, GSMEM_BYTES>>>(ap, wop, bo, out);
}

// round 14
// speedup vs baseline: 2.0694x; 2.0694x over previous
#include <cuda_runtime.h>
#include <cuda_fp16.h>
#include <cstdint>
#include <math.h>

// ---------------- problem constants ----------------
#define BATCH 2
#define SEQ   2048
#define DM    1024
#define NH    16
#define DH    64
#define MROWS (BATCH*SEQ)   // 4096

// ---------------- scratch ----------------
__device__ __half g_Q [(size_t)BATCH*NH*SEQ*DH];   // [b][h][t][dh]
__device__ __half g_K [(size_t)BATCH*NH*SEQ*DH];   // [b][h][t][dh]
__device__ __half g_Vt[(size_t)BATCH*NH*DH*SEQ];   // [b][h][dh][t]  (transposed!)
__device__ __half g_A [(size_t)MROWS*DM];          // attn out, half
__device__ __half g_X [(size_t)MROWS*DM];          // x in half
__device__ __half g_Wq[(size_t)DM*DM];
__device__ __half g_Wk[(size_t)DM*DM];
__device__ __half g_Wv[(size_t)DM*DM];
__device__ __half g_Wo[(size_t)DM*DM];

__device__ __forceinline__ void mma_f16(float* d, const uint32_t* a, uint32_t b0, uint32_t b1) {
    asm volatile(
        "mma.sync.aligned.m16n8k16.row.col.f32.f16.f16.f32 "
        "{%0,%1,%2,%3}, {%4,%5,%6,%7}, {%8,%9}, {%0,%1,%2,%3};"
        : "+f"(d[0]), "+f"(d[1]), "+f"(d[2]), "+f"(d[3])
        : "r"(a[0]), "r"(a[1]), "r"(a[2]), "r"(a[3]), "r"(b0), "r"(b1));
}
__device__ __forceinline__ uint32_t pack_h2(float lo, float hi) {
    __half2 h = __floats2half2_rn(lo, hi);
    return *(uint32_t*)&h;
}

// ---------------- prepass: f32 -> f16 for x and all weights ----------------
#define NX ((size_t)MROWS*DM)
#define NW ((size_t)DM*DM)
#define NTOT (NX + 4*NW)     // 8388608 floats

__global__ __launch_bounds__(256)
void prep_kernel(const float* __restrict__ x,
                 const float* __restrict__ Wq, const float* __restrict__ Wk,
                 const float* __restrict__ Wv, const float* __restrict__ Wo,
                 __half* __restrict__ gx,
                 __half* __restrict__ gwq, __half* __restrict__ gwk,
                 __half* __restrict__ gwv, __half* __restrict__ gwo)
{
    size_t v = (size_t)blockIdx.x * blockDim.x + threadIdx.x;   // float4 index
    const size_t nx4 = NX / 4, nw4 = NW / 4;
    if (v >= NTOT / 4) return;
    const float4* src; __half* dst; size_t off;
    if (v < nx4)              { src = (const float4*)x;  dst = gx;  off = v; }
    else if (v < nx4 + nw4)   { src = (const float4*)Wq; dst = gwq; off = v - nx4; }
    else if (v < nx4 + 2*nw4) { src = (const float4*)Wk; dst = gwk; off = v - nx4 - nw4; }
    else if (v < nx4 + 3*nw4) { src = (const float4*)Wv; dst = gwv; off = v - nx4 - 2*nw4; }
    else                      { src = (const float4*)Wo; dst = gwo; off = v - nx4 - 3*nw4; }
    float4 a = src[off];
    uint2 o;
    o.x = pack_h2(a.x, a.y);
    o.y = pack_h2(a.z, a.w);
    ((uint2*)dst)[off] = o;
}

// ---------------- fp16 HMMA GEMM: C = A(MxK) * W(NxK)^T + bias ----------------
// CTA 128x128, K-chunk 64 halves, double-buffered row-major half tiles (ld 72).
// 8 warps = 4(m) x 2(n); warp tile 32x64; m16n8k16.
#define GM 128
#define GN 128
#define GKC 64
#define NCHUNK (DM/GKC)       // 16
#define GLD 72                // halves per row (uint32 stride 36 -> conflict-free frags)
#define GTILE_H (128*GLD)     // halves per tile

// smem bytes: bias f32[128] | A0 | B0 | A1 | B1
#define GOFF_BIAS 0
#define GOFF_A0   512
#define GOFF_B0   (GOFF_A0 + GTILE_H*2)
#define GOFF_A1   (GOFF_B0 + GTILE_H*2)
#define GOFF_B1   (GOFF_A1 + GTILE_H*2)
#define GSMEM_BYTES (GOFF_B1 + GTILE_H*2)   // 74240

// modes: 0 = f32 row-major (final); 1 = K rotate->half [b][h][t][dh];
//        2 = V ->half TRANSPOSED [b][h][dh][t]; 3 = Q rotate+0.125->half [b][h][t][dh]
__device__ __forceinline__
void gemm_body(char* smem, const __half* __restrict__ A, const __half* __restrict__ W,
               const float* __restrict__ bias, float* __restrict__ Cf,
               __half* __restrict__ Ch, int mode)
{
    float*  bs  = (float*)(smem + GOFF_BIAS);
    const int tid  = threadIdx.x;
    const int lane = tid & 31;
    const int wid  = tid >> 5;
    const int wm   = wid & 3;
    const int wn   = wid >> 2;
    const int m0   = blockIdx.y * GM;
    const int n0   = blockIdx.x * GN;
    const int g    = lane >> 2;
    const int t    = lane & 3;

    if (tid < 128) bs[tid] = bias[n0 + tid];

    const int srow = tid >> 1;          // 0..127
    const int sseg = (tid & 1) * 32;    // halves

    // ---- stage chunk 0 ----
    uint4 ra[4], rw[4];
    {
        const __half* Ac = A + (size_t)(m0 + srow) * DM + sseg;
        const __half* Wc = W + (size_t)(n0 + srow) * DM + sseg;
        #pragma unroll
        for (int i = 0; i < 4; i++) {
            ra[i] = ((const uint4*)Ac)[i];
            rw[i] = ((const uint4*)Wc)[i];
        }
    }
    {
        uint4* ad = (uint4*)((__half*)(smem + GOFF_A0) + srow * GLD + sseg);
        uint4* bd = (uint4*)((__half*)(smem + GOFF_B0) + srow * GLD + sseg);
        #pragma unroll
        for (int i = 0; i < 4; i++) { ad[i] = ra[i]; bd[i] = rw[i]; }
    }
    __syncthreads();

    float acc[2][8][4];
    #pragma unroll
    for (int mt = 0; mt < 2; mt++)
        #pragma unroll
        for (int nt = 0; nt < 8; nt++)
            #pragma unroll
            for (int e = 0; e < 4; e++) acc[mt][nt][e] = 0.f;

    for (int c = 0; c < NCHUNK; c++) {
        const int p = c & 1;
        const uint32_t* A32 = (const uint32_t*)(smem + (p ? GOFF_A1 : GOFF_A0));
        const uint32_t* B32 = (const uint32_t*)(smem + (p ? GOFF_B1 : GOFF_B0));

        if (c + 1 < NCHUNK) {
            const __half* Ac = A + (size_t)(m0 + srow) * DM + (c + 1) * GKC + sseg;
            const __half* Wc = W + (size_t)(n0 + srow) * DM + (c + 1) * GKC + sseg;
            #pragma unroll
            for (int i = 0; i < 4; i++) {
                ra[i] = ((const uint4*)Ac)[i];
                rw[i] = ((const uint4*)Wc)[i];
            }
        }

        #pragma unroll
        for (int ks = 0; ks < 4; ks++) {
            uint32_t af[2][4];
            #pragma unroll
            for (int mt = 0; mt < 2; mt++) {
                const int r0 = (wm * 32 + mt * 16 + g) * 36 + ks * 8 + t;
                af[mt][0] = A32[r0];
                af[mt][1] = A32[r0 + 8 * 36];
                af[mt][2] = A32[r0 + 4];
                af[mt][3] = A32[r0 + 8 * 36 + 4];
            }
            #pragma unroll
            for (int nt = 0; nt < 8; nt++) {
                const int rb = (wn * 64 + nt * 8 + g) * 36 + ks * 8 + t;
                uint32_t b0 = B32[rb], b1 = B32[rb + 4];
                mma_f16(acc[0][nt], af[0], b0, b1);
                mma_f16(acc[1][nt], af[1], b0, b1);
            }
        }

        if (c + 1 < NCHUNK) {
            uint4* ad = (uint4*)((__half*)(smem + (p ? GOFF_A0 : GOFF_A1)) + srow * GLD + sseg);
            uint4* bd = (uint4*)((__half*)(smem + (p ? GOFF_B0 : GOFF_B1)) + srow * GLD + sseg);
            #pragma unroll
            for (int i = 0; i < 4; i++) { ad[i] = ra[i]; bd[i] = rw[i]; }
        }
        __syncthreads();
    }

    // ---- epilogue ----
    #pragma unroll
    for (int mt = 0; mt < 2; mt++) {
        #pragma unroll
        for (int nt = 0; nt < 8; nt++) {
            const int colL = wn * 64 + nt * 8 + t * 2;
            const int col  = n0 + colL;
            #pragma unroll
            for (int half_ = 0; half_ < 2; half_++) {
                const int m = m0 + wm * 32 + mt * 16 + g + half_ * 8;
                float y0 = acc[mt][nt][half_ * 2 + 0] + bs[colL];
                float y1 = acc[mt][nt][half_ * 2 + 1] + bs[colL + 1];
                if (mode == 0) {
                    *(float2*)(Cf + (size_t)m * DM + col) = make_float2(y0, y1);
                } else {
                    const int b  = m >> 11;
                    const int ts = m & 2047;
                    const int h  = col >> 6;
                    const int dh = col & 63;
                    if (mode == 2) {
                        // V transposed: [b][h][dh][t]
                        __half* vt = Ch + ((size_t)(b * NH + h) * DH) * SEQ;
                        vt[(size_t)dh * SEQ + ts]       = __float2half_rn(y0);
                        vt[(size_t)(dh + 1) * SEQ + ts] = __float2half_rn(y1);
                    } else {
                        uint32_t o = (mode == 3) ? pack_h2(-y1 * 0.125f, y0 * 0.125f)
                                                 : pack_h2(-y1, y0);
                        *(uint32_t*)(Ch + (((size_t)(b * NH + h) * SEQ) + ts) * DH + dh) = o;
                    }
                }
            }
        }
    }
}

__global__ __launch_bounds__(256, 2)
void gemm_qkv_kernel(const __half* __restrict__ x,
                     const __half* __restrict__ Wq, const float* __restrict__ bq,
                     const __half* __restrict__ Wk, const float* __restrict__ bk,
                     const __half* __restrict__ Wv, const float* __restrict__ bv,
                     __half* __restrict__ Qo, __half* __restrict__ Ko, __half* __restrict__ Vo)
{
    extern __shared__ char smem[];
    const int z = blockIdx.z;
    const __half* W    = (z == 0) ? Wq : (z == 1) ? Wk : Wv;
    const float* bias  = (z == 0) ? bq : (z == 1) ? bk : bv;
    __half* C          = (z == 0) ? Qo : (z == 1) ? Ko : Vo;
    gemm_body(smem, x, W, bias, nullptr, C, (z == 0) ? 3 : (z == 1) ? 1 : 2);
}

__global__ __launch_bounds__(256, 2)
void gemm_o_kernel(const __half* __restrict__ A, const __half* __restrict__ W,
                   const float* __restrict__ bias, float* __restrict__ C)
{
    extern __shared__ char smem[];
    gemm_body(smem, A, W, bias, C, nullptr, 0);
}

// ---------------- fp16 HMMA flash attention ----------------
// CTA: 128 q-rows, 4 warps x 32 rows (2 mtiles). KV tiles of 64 keys. m16n8k16.
// smem halves: Qs[128][72] | Ks[64][72] (row=key) | Vt[64][72] (row=dh)
#define ALD 72
#define A_OFF_Q 0
#define A_OFF_K (128*ALD*2)                 // bytes
#define A_OFF_V (A_OFF_K + 64*ALD*2)
#define A_SMEM_BYTES (A_OFF_V + 64*ALD*2)   // 36864

__global__ __launch_bounds__(128, 3)
void attn_mma_kernel(const __half* __restrict__ Q, const __half* __restrict__ K,
                     const __half* __restrict__ Vt, __half* __restrict__ O)
{
    extern __shared__ char smem[];
    __half* Qs = (__half*)(smem + A_OFF_Q);
    __half* Ks = (__half*)(smem + A_OFF_K);
    __half* Vs = (__half*)(smem + A_OFF_V);
    const uint32_t* Q32 = (const uint32_t*)Qs;
    const uint32_t* K32 = (const uint32_t*)Ks;
    const uint32_t* V32 = (const uint32_t*)Vs;

    const int tid  = threadIdx.x;
    const int lane = tid & 31;
    const int w    = tid >> 5;
    const int g    = lane >> 2;
    const int t    = lane & 3;
    const int bh   = blockIdx.y;
    const int qb   = (gridDim.x - 1) - blockIdx.x;   // heavy blocks first
    const int qblk = qb * 128;

    const __half* Qg  = Q  + (size_t)bh * SEQ * DH;
    const __half* Kg  = K  + (size_t)bh * SEQ * DH;
    const __half* Vtg = Vt + (size_t)bh * DH * SEQ;

    // ---- stage Q (pre-scaled/rounded halves): 1024 uint4 units ----
    {
        const __half* src = Qg + (size_t)qblk * DH;
        #pragma unroll
        for (int j = 0; j < 8; j++) {
            const int f = tid + j * 128;         // uint4 unit
            const int row = f >> 3, seg = f & 7; // 8 halves per unit
            *(uint4*)(Qs + row * ALD + seg * 8) = *(const uint4*)(src + row * DH + seg * 8);
        }
    }

    float o[2][8][4];
    #pragma unroll
    for (int mt = 0; mt < 2; mt++)
        #pragma unroll
        for (int nt = 0; nt < 8; nt++)
            #pragma unroll
            for (int e = 0; e < 4; e++) o[mt][nt][e] = 0.f;
    float mrow[2][2] = {{-1e30f, -1e30f}, {-1e30f, -1e30f}};
    float lrow[2][2] = {{0.f, 0.f}, {0.f, 0.f}};

    const int ntiles = 2 * qb + 2;
    const int wrow   = qblk + w * 32;
    const int wmax   = wrow + 31;

    for (int kt = 0; kt < ntiles; kt++) {
        const int kbase = kt * 64;
        __syncthreads();
        // ---- stage K [key][d] and Vt [d][key]: 512 uint4 units each ----
        {
            #pragma unroll
            for (int j = 0; j < 4; j++) {
                const int f = tid + j * 128;
                const int row = f >> 3, seg = f & 7;
                *(uint4*)(Ks + row * ALD + seg * 8) =
                    *(const uint4*)(Kg + (size_t)(kbase + row) * DH + seg * 8);
                *(uint4*)(Vs + row * ALD + seg * 8) =
                    *(const uint4*)(Vtg + (size_t)row * SEQ + kbase + seg * 8);
            }
        }
        __syncthreads();
        if (kbase > wmax) continue;

        // ---- S = Q K^T : 4 ksteps of 16 over DH ----
        float s[2][8][4];
        #pragma unroll
        for (int mt = 0; mt < 2; mt++)
            #pragma unroll
            for (int nt = 0; nt < 8; nt++)
                #pragma unroll
                for (int e = 0; e < 4; e++) s[mt][nt][e] = 0.f;

        #pragma unroll
        for (int ks = 0; ks < 4; ks++) {
            uint32_t af[2][4];
            #pragma unroll
            for (int mt = 0; mt < 2; mt++) {
                const int r0 = (w * 32 + mt * 16 + g) * 36 + ks * 8 + t;
                af[mt][0] = Q32[r0];
                af[mt][1] = Q32[r0 + 8 * 36];
                af[mt][2] = Q32[r0 + 4];
                af[mt][3] = Q32[r0 + 8 * 36 + 4];
            }
            #pragma unroll
            for (int nt = 0; nt < 8; nt++) {
                const int rb = (nt * 8 + g) * 36 + ks * 8 + t;
                uint32_t b0 = K32[rb], b1 = K32[rb + 4];
                mma_f16(s[0][nt], af[0], b0, b1);
                mma_f16(s[1][nt], af[1], b0, b1);
            }
        }

        // ---- causal mask ----
        if (kbase + 63 > wrow) {
            #pragma unroll
            for (int mt = 0; mt < 2; mt++) {
                const int r0 = wrow + mt * 16 + g;
                const int r1 = r0 + 8;
                #pragma unroll
                for (int nt = 0; nt < 8; nt++) {
                    const int key = kbase + nt * 8 + 2 * t;
                    if (key     > r0) s[mt][nt][0] = -1e30f;
                    if (key + 1 > r0) s[mt][nt][1] = -1e30f;
                    if (key     > r1) s[mt][nt][2] = -1e30f;
                    if (key + 1 > r1) s[mt][nt][3] = -1e30f;
                }
            }
        }

        // ---- online softmax ----
        #pragma unroll
        for (int mt = 0; mt < 2; mt++) {
            float mx0 = -1e30f, mx1 = -1e30f;
            #pragma unroll
            for (int nt = 0; nt < 8; nt++) {
                mx0 = fmaxf(mx0, fmaxf(s[mt][nt][0], s[mt][nt][1]));
                mx1 = fmaxf(mx1, fmaxf(s[mt][nt][2], s[mt][nt][3]));
            }
            mx0 = fmaxf(mx0, __shfl_xor_sync(0xFFFFFFFFu, mx0, 1));
            mx0 = fmaxf(mx0, __shfl_xor_sync(0xFFFFFFFFu, mx0, 2));
            mx1 = fmaxf(mx1, __shfl_xor_sync(0xFFFFFFFFu, mx1, 1));
            mx1 = fmaxf(mx1, __shfl_xor_sync(0xFFFFFFFFu, mx1, 2));
            const float mn0 = fmaxf(mrow[mt][0], mx0);
            const float mn1 = fmaxf(mrow[mt][1], mx1);
            const float c0 = __expf(mrow[mt][0] - mn0);
            const float c1 = __expf(mrow[mt][1] - mn1);
            lrow[mt][0] *= c0; lrow[mt][1] *= c1;
            #pragma unroll
            for (int nt = 0; nt < 8; nt++) {
                o[mt][nt][0] *= c0; o[mt][nt][1] *= c0;
                o[mt][nt][2] *= c1; o[mt][nt][3] *= c1;
            }
            mrow[mt][0] = mn0; mrow[mt][1] = mn1;
            float rs0 = 0.f, rs1 = 0.f;
            #pragma unroll
            for (int nt = 0; nt < 8; nt++) {
                s[mt][nt][0] = __expf(s[mt][nt][0] - mn0);
                s[mt][nt][1] = __expf(s[mt][nt][1] - mn0);
                s[mt][nt][2] = __expf(s[mt][nt][2] - mn1);
                s[mt][nt][3] = __expf(s[mt][nt][3] - mn1);
                rs0 += s[mt][nt][0] + s[mt][nt][1];
                rs1 += s[mt][nt][2] + s[mt][nt][3];
            }
            rs0 += __shfl_xor_sync(0xFFFFFFFFu, rs0, 1);
            rs0 += __shfl_xor_sync(0xFFFFFFFFu, rs0, 2);
            rs1 += __shfl_xor_sync(0xFFFFFFFFu, rs1, 1);
            rs1 += __shfl_xor_sync(0xFFFFFFFFu, rs1, 2);
            lrow[mt][0] += rs0; lrow[mt][1] += rs1;
        }

        // ---- O += P V : P's C-layout == fp16 A-fragment layout; NO shuffles ----
        #pragma unroll
        for (int ks = 0; ks < 4; ks++) {
            uint32_t af[2][4];
            #pragma unroll
            for (int mt = 0; mt < 2; mt++) {
                af[mt][0] = pack_h2(s[mt][2*ks    ][0], s[mt][2*ks    ][1]);
                af[mt][1] = pack_h2(s[mt][2*ks    ][2], s[mt][2*ks    ][3]);
                af[mt][2] = pack_h2(s[mt][2*ks + 1][0], s[mt][2*ks + 1][1]);
                af[mt][3] = pack_h2(s[mt][2*ks + 1][2], s[mt][2*ks + 1][3]);
            }
            #pragma unroll
            for (int dnt = 0; dnt < 8; dnt++) {
                const int rb = (dnt * 8 + g) * 36 + ks * 8 + t;
                uint32_t b0 = V32[rb], b1 = V32[rb + 4];
                mma_f16(o[0][dnt], af[0], b0, b1);
                mma_f16(o[1][dnt], af[1], b0, b1);
            }
        }
    }

    // ---- normalize + write half2 -> g_A [b][t][h*64+dh] ----
    const int b = bh >> 4, h = bh & 15;
    #pragma unroll
    for (int mt = 0; mt < 2; mt++) {
        const float i0 = 1.f / lrow[mt][0];
        const float i1 = 1.f / lrow[mt][1];
        const int r0 = wrow + mt * 16 + g;
        const int r1 = r0 + 8;
        #pragma unroll
        for (int dnt = 0; dnt < 8; dnt++) {
            const int col = h * 64 + dnt * 8 + 2 * t;
            *(uint32_t*)(O + ((size_t)(b * SEQ + r0)) * DM + col) =
                pack_h2(o[mt][dnt][0] * i0, o[mt][dnt][1] * i0);
            *(uint32_t*)(O + ((size_t)(b * SEQ + r1)) * DM + col) =
                pack_h2(o[mt][dnt][2] * i1, o[mt][dnt][3] * i1);
        }
    }
}

// ---------------- launcher ----------------
extern "C" void kernel_launch(void* const* d_in, const int* in_sizes, int n_in,
                              void* d_out, int out_size)
{
    const float* x  = (const float*)d_in[0];
    const float* Wq = (const float*)d_in[1];
    const float* bq = (const float*)d_in[2];
    const float* Wk = (const float*)d_in[3];
    const float* bk = (const float*)d_in[4];
    const float* Wv = (const float*)d_in[5];
    const float* bv = (const float*)d_in[6];
    const float* Wo = (const float*)d_in[7];
    const float* bo = (const float*)d_in[8];
    float* out = (float*)d_out;

    __half *qp, *kp, *vtp, *ap, *xp, *wqp, *wkp, *wvp, *wop;
    cudaGetSymbolAddress((void**)&qp,  g_Q);
    cudaGetSymbolAddress((void**)&kp,  g_K);
    cudaGetSymbolAddress((void**)&vtp, g_Vt);
    cudaGetSymbolAddress((void**)&ap,  g_A);
    cudaGetSymbolAddress((void**)&xp,  g_X);
    cudaGetSymbolAddress((void**)&wqp, g_Wq);
    cudaGetSymbolAddress((void**)&wkp, g_Wk);
    cudaGetSymbolAddress((void**)&wvp, g_Wv);
    cudaGetSymbolAddress((void**)&wop, g_Wo);

    cudaFuncSetAttribute(gemm_qkv_kernel, cudaFuncAttributeMaxDynamicSharedMemorySize, GSMEM_BYTES);
    cudaFuncSetAttribute(gemm_o_kernel,  cudaFuncAttributeMaxDynamicSharedMemorySize, GSMEM_BYTES);
    cudaFuncSetAttribute(attn_mma_kernel, cudaFuncAttributeMaxDynamicSharedMemorySize, A_SMEM_BYTES);

    // prepass: f32 -> f16 once
    {
        const int nthreads = 256;
        const int nblocks = (int)((NTOT / 4 + nthreads - 1) / nthreads);
        prep_kernel<<<nblocks, nthreads>>>(x, Wq, Wk, Wv, Wo, xp, wqp, wkp, wvp, wop);
    }

    dim3 gq(DM / GN, MROWS / GM, 3);   // (8, 32, 3)
    gemm_qkv_kernel<<<gq, 256, GSMEM_BYTES>>>(xp, wqp, bq, wkp, bk, wvp, bv, qp, kp, vtp);

    attn_mma_kernel<<<dim3(SEQ / 128, BATCH * NH), 128, A_SMEM_BYTES>>>(qp, kp, vtp, ap);

    dim3 gg(DM / GN, MROWS / GM);      // (8, 32)
    gemm_o_kernel<<<gg, 256, GSMEM_BYTES>>>(ap, wop, bo, out);
}